// round 1
// baseline (speedup 1.0000x reference)
#include <cuda_runtime.h>
#include <cuda_bf16.h>
#include <math.h>

#define TOKENS 8192
#define DIM    4096
#define NEXP   256
#define TOPK   8

#define TM 16      // tokens per CTA
#define BK 32      // K chunk
#define NTHREADS 256

// smem pool: staging (x_s 32*16 + w_s 32*256 = 8704 floats) reused as logits (16*256 = 4096)
#define POOL_FLOATS (BK*TM + BK*NEXP)

__global__ __launch_bounds__(NTHREADS)
void gate_fp32_kernel(const float* __restrict__ x,
                      const float* __restrict__ w,
                      float* __restrict__ out,
                      int write_idx)
{
    __shared__ float pool[POOL_FLOATS];
    float* x_s = pool;              // [BK][TM]
    float* w_s = pool + BK * TM;    // [BK][NEXP]

    const int tid = threadIdx.x;
    const int tx  = tid & 63;       // expert quad: experts tx*4..tx*4+3
    const int ty  = tid >> 6;       // token quad:  tokens ty*4..ty*4+3
    const int t0  = blockIdx.x * TM;

    float acc[4][4];
    #pragma unroll
    for (int m = 0; m < 4; ++m)
        #pragma unroll
        for (int n = 0; n < 4; ++n) acc[m][n] = 0.f;

    // staging-load thread mappings
    const int x_tok = tid >> 4;          // 0..15
    const int x_kk  = (tid & 15) * 2;    // 0,2,..,30
    const int w_ein = tid >> 3;          // 0..31
    const int w_ko  = (tid & 7) * 4;     // 0,4,..,28

    for (int kc = 0; kc < DIM; kc += BK) {
        __syncthreads();
        // ---- stage x tile [TM][BK] -> x_s[k][tok] ----
        {
            float2 v = *(const float2*)(x + (size_t)(t0 + x_tok) * DIM + kc + x_kk);
            x_s[(x_kk + 0) * TM + x_tok] = v.x;
            x_s[(x_kk + 1) * TM + x_tok] = v.y;
        }
        // ---- stage w tile [NEXP][BK] -> w_s[k][e] ----
        #pragma unroll
        for (int it = 0; it < 8; ++it) {
            int e = it * 32 + w_ein;
            float4 v = *(const float4*)(w + (size_t)e * DIM + kc + w_ko);
            w_s[(w_ko + 0) * NEXP + e] = v.x;
            w_s[(w_ko + 1) * NEXP + e] = v.y;
            w_s[(w_ko + 2) * NEXP + e] = v.z;
            w_s[(w_ko + 3) * NEXP + e] = v.w;
        }
        __syncthreads();

        // ---- compute: 32 k-steps x 16 FMA ----
        #pragma unroll 8
        for (int k = 0; k < BK; ++k) {
            float4 xv = *(const float4*)(x_s + k * TM + ty * 4);
            float4 wv = *(const float4*)(w_s + k * NEXP + tx * 4);
            acc[0][0] = fmaf(xv.x, wv.x, acc[0][0]);
            acc[0][1] = fmaf(xv.x, wv.y, acc[0][1]);
            acc[0][2] = fmaf(xv.x, wv.z, acc[0][2]);
            acc[0][3] = fmaf(xv.x, wv.w, acc[0][3]);
            acc[1][0] = fmaf(xv.y, wv.x, acc[1][0]);
            acc[1][1] = fmaf(xv.y, wv.y, acc[1][1]);
            acc[1][2] = fmaf(xv.y, wv.z, acc[1][2]);
            acc[1][3] = fmaf(xv.y, wv.w, acc[1][3]);
            acc[2][0] = fmaf(xv.z, wv.x, acc[2][0]);
            acc[2][1] = fmaf(xv.z, wv.y, acc[2][1]);
            acc[2][2] = fmaf(xv.z, wv.z, acc[2][2]);
            acc[2][3] = fmaf(xv.z, wv.w, acc[2][3]);
            acc[3][0] = fmaf(xv.w, wv.x, acc[3][0]);
            acc[3][1] = fmaf(xv.w, wv.y, acc[3][1]);
            acc[3][2] = fmaf(xv.w, wv.z, acc[3][2]);
            acc[3][3] = fmaf(xv.w, wv.w, acc[3][3]);
        }
    }

    // ---- epilogue: logits to smem (reuse pool) ----
    __syncthreads();
    float* lg = pool;   // [TM][NEXP]
    #pragma unroll
    for (int m = 0; m < 4; ++m)
        #pragma unroll
        for (int n = 0; n < 4; ++n)
            lg[(ty * 4 + m) * NEXP + (tx * 4 + n)] = acc[m][n];
    __syncthreads();

    // ---- top-8 per token: 1 warp handles 2 tokens ----
    const int warp = tid >> 5;
    const int lane = tid & 31;

    #pragma unroll
    for (int tt = 0; tt < 2; ++tt) {
        const int t = warp * 2 + tt;     // local token 0..15
        float v[8];
        #pragma unroll
        for (int j = 0; j < 8; ++j) v[j] = lg[t * NEXP + lane + j * 32];

        float topv[8];
        int   topi[8];
        unsigned used = 0;

        #pragma unroll
        for (int r = 0; r < 8; ++r) {
            float best = -INFINITY;
            int   bidx = 0x7fffffff;
            #pragma unroll
            for (int j = 0; j < 8; ++j) {
                if (!((used >> j) & 1u)) {
                    float val = v[j];
                    int   id  = lane + j * 32;
                    if (val > best || (val == best && id < bidx)) { best = val; bidx = id; }
                }
            }
            #pragma unroll
            for (int off = 16; off > 0; off >>= 1) {
                float ov = __shfl_xor_sync(0xffffffffu, best, off);
                int   oi = __shfl_xor_sync(0xffffffffu, bidx, off);
                if (ov > best || (ov == best && oi < bidx)) { best = ov; bidx = oi; }
            }
            topv[r] = best;
            topi[r] = bidx;
            if ((bidx & 31) == lane) used |= 1u << (bidx >> 5);
        }

        // gates = sigmoid(topv) / sum(sigmoid(topv))
        float s[8], sum = 0.f;
        #pragma unroll
        for (int r = 0; r < 8; ++r) {
            s[r] = 1.f / (1.f + expf(-topv[r]));
            sum += s[r];
        }
        float inv = 1.f / sum;

        if (lane == 0) {
            int gt = t0 + t;
            #pragma unroll
            for (int r = 0; r < 8; ++r)
                out[(size_t)gt * TOPK + r] = s[r] * inv;
            if (write_idx) {
                #pragma unroll
                for (int r = 0; r < 8; ++r)
                    out[(size_t)TOKENS * TOPK + (size_t)gt * TOPK + r] = (float)topi[r];
            }
        }
    }
}

extern "C" void kernel_launch(void* const* d_in, const int* in_sizes, int n_in,
                              void* d_out, int out_size)
{
    const float* x = (const float*)d_in[0];   // [TOKENS, DIM]
    const float* w = (const float*)d_in[1];   // [NEXP, DIM]
    float* out = (float*)d_out;

    int write_idx = (out_size >= 2 * TOKENS * TOPK) ? 1 : 0;

    dim3 grid(TOKENS / TM);
    dim3 block(NTHREADS);
    gate_fp32_kernel<<<grid, block>>>(x, w, out, write_idx);
}

// round 5
// speedup vs baseline: 1.9145x; 1.9145x over previous
#include <cuda_runtime.h>
#include <cuda_bf16.h>
#include <math.h>
#include <stdint.h>

#define TOKENS 8192
#define DIM    4096
#define NEXP   256
#define TOPK   8

#define TM   64
#define BK   32                 // 2 x k16 per chunk
#define NCH  (DIM / BK)         // 128
#define NTH  512

#define ROWB    224             // bytes per row: 3 splits x 64B + 32B pad (conflict-free: 224/4=56==24 mod 32)
#define ST_A    0
#define ST_B    (64 * ROWB)             // 14336
#define STAGE   (ST_B + 256 * ROWB)     // 71680
#define SMEM_BYTES (2 * STAGE)          // 143360
#define LGS  264

// pre-split W: per (n, kc32) a 192B block: [split sp][cq 0..1][2 x uint4]
__device__ __align__(16) char g_wb[NEXP * NCH * 192];

__device__ __forceinline__ uint32_t pack_bf16(__nv_bfloat16 lo, __nv_bfloat16 hi) {
    return ((uint32_t)__bfloat16_as_ushort(hi) << 16) | __bfloat16_as_ushort(lo);
}

__device__ __forceinline__ void mma_bf16(float* d,
                                         uint32_t a0, uint32_t a1, uint32_t a2, uint32_t a3,
                                         uint32_t b0, uint32_t b1) {
    asm volatile(
        "mma.sync.aligned.m16n8k16.row.col.f32.bf16.bf16.f32 "
        "{%0,%1,%2,%3},{%4,%5,%6,%7},{%8,%9},{%0,%1,%2,%3};"
        : "+f"(d[0]), "+f"(d[1]), "+f"(d[2]), "+f"(d[3])
        : "r"(a0), "r"(a1), "r"(a2), "r"(a3), "r"(b0), "r"(b1));
}

__device__ __forceinline__ uint32_t smem_u32(const void* p) {
    uint32_t a;
    asm("{ .reg .u64 t; cvta.to.shared.u64 t, %1; cvt.u32.u64 %0, t; }" : "=r"(a) : "l"(p));
    return a;
}
#define CP_ASYNC16(dst, src) \
    asm volatile("cp.async.cg.shared.global [%0], [%1], 16;" :: "r"(dst), "l"(src))
#define CP_COMMIT() asm volatile("cp.async.commit_group;" ::: "memory")
#define CP_WAIT0()  asm volatile("cp.async.wait_group 0;" ::: "memory")

// 3-way bf16 split of 16 consecutive fp32, packed as pair-quads into a 192B block layout
__device__ __forceinline__ void split16_store(const float* v, char* blk) {
    uint32_t Ph[8], Pm[8], Pl[8];
    #pragma unroll
    for (int j = 0; j < 8; ++j) {
        float v0 = v[2 * j], v1 = v[2 * j + 1];
        __nv_bfloat16 h0 = __float2bfloat16_rn(v0);
        __nv_bfloat16 h1 = __float2bfloat16_rn(v1);
        float r0 = v0 - __bfloat162float(h0);
        float r1 = v1 - __bfloat162float(h1);
        __nv_bfloat16 m0 = __float2bfloat16_rn(r0);
        __nv_bfloat16 m1 = __float2bfloat16_rn(r1);
        __nv_bfloat16 l0 = __float2bfloat16_rn(r0 - __bfloat162float(m0));
        __nv_bfloat16 l1 = __float2bfloat16_rn(r1 - __bfloat162float(m1));
        Ph[j] = pack_bf16(h0, h1);
        Pm[j] = pack_bf16(m0, m1);
        Pl[j] = pack_bf16(l0, l1);
    }
    uint4* p = (uint4*)blk;                 // split h at +0
    p[0] = make_uint4(Ph[0], Ph[4], Ph[1], Ph[5]);
    p[1] = make_uint4(Ph[2], Ph[6], Ph[3], Ph[7]);
    p = (uint4*)(blk + 64);                 // split m
    p[0] = make_uint4(Pm[0], Pm[4], Pm[1], Pm[5]);
    p[1] = make_uint4(Pm[2], Pm[6], Pm[3], Pm[7]);
    p = (uint4*)(blk + 128);                // split l
    p[0] = make_uint4(Pl[0], Pl[4], Pl[1], Pl[5]);
    p[1] = make_uint4(Pl[2], Pl[6], Pl[3], Pl[7]);
}

// XLA logistic: 0.5 + 0.5 * tanh(0.5x), tanh = Eigen/XLA f32 rational approx
__device__ __forceinline__ float xla_sigmoid(float v) {
    float x = 0.5f * v;
    float t;
    if (fabsf(x) < 0.0004f) {
        t = x;
    } else {
        float xc = fminf(fmaxf(x, -7.90531110763549805f), 7.90531110763549805f);
        float x2 = xc * xc;
        float p = -2.76076847742355e-16f;
        p = fmaf(p, x2, 2.00018790482477e-13f);
        p = fmaf(p, x2, -8.60467152213735e-11f);
        p = fmaf(p, x2, 5.12229709037114e-08f);
        p = fmaf(p, x2, 1.48572235717979e-05f);
        p = fmaf(p, x2, 6.37261928875436e-04f);
        p = fmaf(p, x2, 4.89352455891786e-03f);
        p = xc * p;
        float q = 1.19825839466702e-06f;
        q = fmaf(q, x2, 1.18534705686654e-04f);
        q = fmaf(q, x2, 2.26843463243900e-03f);
        q = fmaf(q, x2, 4.89352518554385e-03f);
        t = p / q;
    }
    return fmaf(0.5f, t, 0.5f);
}

// ============================================================================
// W pre-split: thread per (n, kc32)
// ============================================================================
__global__ __launch_bounds__(256) void wsplit_kernel(const float* __restrict__ w) {
    int j = blockIdx.x * 256 + threadIdx.x;   // 32768
    int kc = j & 127;
    int n  = j >> 7;
    float v[32];
    const float4* src = (const float4*)(w + (size_t)n * DIM + kc * BK);
    #pragma unroll
    for (int i = 0; i < 8; ++i) {
        float4 f = src[i];
        v[i * 4 + 0] = f.x; v[i * 4 + 1] = f.y; v[i * 4 + 2] = f.z; v[i * 4 + 3] = f.w;
    }
    char* blk = g_wb + (size_t)j * 192;
    split16_store(v,      blk);        // cq=0 slots at sp*64 + 0
    split16_store(v + 16, blk + 32);   // cq=1 slots at sp*64 + 32
}

// ============================================================================
// main kernel
// ============================================================================
__global__ __launch_bounds__(NTH, 1)
void gate_bf16x3_kernel(const float* __restrict__ x,
                        float* __restrict__ out,
                        int write_idx)
{
    extern __shared__ char smem[];
    const uint32_t sb = smem_u32(smem);
    const int tid    = threadIdx.x;
    const int lane   = tid & 31;
    const int wid    = tid >> 5;
    const int warp_m = wid & 1;      // 2 x 32 tokens
    const int warp_n = wid >> 1;     // 8 x 32 experts
    const int t0     = blockIdx.x * TM;
    const int fr     = lane >> 2;
    const int fc     = lane & 3;

    float am[2][4][4], ac[2][4][4];  // main (hh) and correction accumulators
    #pragma unroll
    for (int tm = 0; tm < 2; ++tm)
        #pragma unroll
        for (int tn = 0; tn < 4; ++tn)
            #pragma unroll
            for (int q = 0; q < 4; ++q) { am[tm][tn][q] = 0.f; ac[tm][tn][q] = 0.f; }

    // fragment load offsets (add stage base + sp*64 + cq*32)
    uint32_t aoff[2][2], boff[4];
    #pragma unroll
    for (int tm = 0; tm < 2; ++tm) {
        int r = warp_m * 32 + tm * 16 + fr;
        aoff[tm][0] = ST_A + r * ROWB + fc * 8;
        aoff[tm][1] = ST_A + (r + 8) * ROWB + fc * 8;
    }
    #pragma unroll
    for (int tn = 0; tn < 4; ++tn)
        boff[tn] = ST_B + (warp_n * 32 + tn * 8 + fr) * ROWB + fc * 8;

    // staging: W cp.async: thread -> (n = tid>>1, half = tid&1, 6 granules)
    const int wn = tid >> 1;
    const int wh = tid & 1;
    // x: threads 0..127: r = tid&63, cq = tid>>6
    const int xr = tid & 63;
    const int xq = (tid >> 6) & 1;

    auto stage = [&](int c, int s) {
        const char* srcw = g_wb + ((size_t)wn * NCH + c) * 192 + wh * 96;
        uint32_t dstw = sb + s * STAGE + ST_B + wn * ROWB + wh * 96;
        #pragma unroll
        for (int g = 0; g < 6; ++g)
            CP_ASYNC16(dstw + g * 16, (const void*)(srcw + g * 16));
        CP_COMMIT();
        if (tid < 128) {
            float v[16];
            const float4* px = (const float4*)(x + (size_t)(t0 + xr) * DIM + c * BK + xq * 16);
            #pragma unroll
            for (int i = 0; i < 4; ++i) {
                float4 f = px[i];
                v[i * 4 + 0] = f.x; v[i * 4 + 1] = f.y; v[i * 4 + 2] = f.z; v[i * 4 + 3] = f.w;
            }
            split16_store(v, smem + s * STAGE + ST_A + xr * ROWB + xq * 32);
        }
    };

    // prologue
    stage(0, 0);
    CP_WAIT0();
    __syncthreads();

    for (int c = 0; c < NCH; ++c) {
        const int s = c & 1;
        if (c + 1 < NCH) stage(c + 1, s ^ 1);

        const char* st = smem + s * STAGE;
        #pragma unroll
        for (int cq = 0; cq < 2; ++cq) {
            const uint32_t co = cq * 32;
            uint2 ah[2][2], amid[2][2], al[2][2];
            #pragma unroll
            for (int tm = 0; tm < 2; ++tm)
                #pragma unroll
                for (int hf = 0; hf < 2; ++hf) {
                    const char* pa = st + aoff[tm][hf] + co;
                    ah[tm][hf]   = *(const uint2*)(pa);
                    amid[tm][hf] = *(const uint2*)(pa + 64);
                    al[tm][hf]   = *(const uint2*)(pa + 128);
                }
            #pragma unroll
            for (int tn = 0; tn < 4; ++tn) {
                const char* pb = st + boff[tn] + co;
                uint2 bh = *(const uint2*)(pb);
                uint2 bm = *(const uint2*)(pb + 64);
                uint2 bl = *(const uint2*)(pb + 128);
                #pragma unroll
                for (int tm = 0; tm < 2; ++tm) {
                    float* dm = am[tm][tn];
                    float* dc = ac[tm][tn];
                    mma_bf16(dm, ah[tm][0].x, ah[tm][1].x, ah[tm][0].y, ah[tm][1].y, bh.x, bh.y);       // hh
                    mma_bf16(dc, ah[tm][0].x, ah[tm][1].x, ah[tm][0].y, ah[tm][1].y, bm.x, bm.y);       // hm
                    mma_bf16(dc, amid[tm][0].x, amid[tm][1].x, amid[tm][0].y, amid[tm][1].y, bh.x, bh.y); // mh
                    mma_bf16(dc, amid[tm][0].x, amid[tm][1].x, amid[tm][0].y, amid[tm][1].y, bm.x, bm.y); // mm
                    mma_bf16(dc, ah[tm][0].x, ah[tm][1].x, ah[tm][0].y, ah[tm][1].y, bl.x, bl.y);       // hl
                    mma_bf16(dc, al[tm][0].x, al[tm][1].x, al[tm][0].y, al[tm][1].y, bh.x, bh.y);       // lh
                }
            }
        }

        CP_WAIT0();
        __syncthreads();
    }

    // ---- epilogue: logits -> smem [64][LGS] ----
    float* lg = (float*)smem;
    #pragma unroll
    for (int tm = 0; tm < 2; ++tm) {
        int r = warp_m * 32 + tm * 16 + fr;
        #pragma unroll
        for (int tn = 0; tn < 4; ++tn) {
            int cc = warp_n * 32 + tn * 8 + fc * 2;
            float v0 = am[tm][tn][0] + ac[tm][tn][0];
            float v1 = am[tm][tn][1] + ac[tm][tn][1];
            float v2 = am[tm][tn][2] + ac[tm][tn][2];
            float v3 = am[tm][tn][3] + ac[tm][tn][3];
            *(float2*)(lg + (size_t)r * LGS + cc)       = make_float2(v0, v1);
            *(float2*)(lg + (size_t)(r + 8) * LGS + cc) = make_float2(v2, v3);
        }
    }
    __syncthreads();

    // ---- top-8 on SIGMOID SCORES with lower-index tie-break (matches jax.lax.top_k) ----
    #pragma unroll
    for (int it = 0; it < 4; ++it) {
        const int t = wid * 4 + it;
        float v[8];
        #pragma unroll
        for (int j = 0; j < 8; ++j)
            v[j] = xla_sigmoid(lg[(size_t)t * LGS + lane + j * 32]);

        float topv[8];
        int   topi[8];
        unsigned used = 0;

        #pragma unroll
        for (int r = 0; r < 8; ++r) {
            float best = -INFINITY;
            int   bidx = 0x7fffffff;
            #pragma unroll
            for (int j = 0; j < 8; ++j) {
                if (!((used >> j) & 1u)) {
                    float val = v[j];
                    int   id  = lane + j * 32;
                    if (val > best || (val == best && id < bidx)) { best = val; bidx = id; }
                }
            }
            #pragma unroll
            for (int off = 16; off > 0; off >>= 1) {
                float ov = __shfl_xor_sync(0xffffffffu, best, off);
                int   oi = __shfl_xor_sync(0xffffffffu, bidx, off);
                if (ov > best || (ov == best && oi < bidx)) { best = ov; bidx = oi; }
            }
            topv[r] = best;
            topi[r] = bidx;
            if ((bidx & 31) == lane) used |= 1u << (bidx >> 5);
        }

        float sum = 0.f;
        #pragma unroll
        for (int r = 0; r < 8; ++r) sum += topv[r];
        float inv = 1.f / sum;

        if (lane == 0) {
            int gt = t0 + t;
            #pragma unroll
            for (int r = 0; r < 8; ++r)
                out[(size_t)gt * TOPK + r] = topv[r] * inv;
            if (write_idx) {
                #pragma unroll
                for (int r = 0; r < 8; ++r)
                    out[(size_t)TOKENS * TOPK + (size_t)gt * TOPK + r] = (float)topi[r];
            }
        }
    }
}

extern "C" void kernel_launch(void* const* d_in, const int* in_sizes, int n_in,
                              void* d_out, int out_size)
{
    const float* x = (const float*)d_in[0];   // [TOKENS, DIM]
    const float* w = (const float*)d_in[1];   // [NEXP, DIM]
    float* out = (float*)d_out;

    int write_idx = (out_size >= 2 * TOKENS * TOPK) ? 1 : 0;

    cudaFuncSetAttribute(gate_bf16x3_kernel, cudaFuncAttributeMaxDynamicSharedMemorySize, SMEM_BYTES);

    wsplit_kernel<<<(NEXP * NCH) / 256, 256>>>(w);
    gate_bf16x3_kernel<<<TOKENS / TM, NTH, SMEM_BYTES>>>(x, out, write_idx);
}

// round 6
// speedup vs baseline: 3.0018x; 1.5679x over previous
#include <cuda_runtime.h>
#include <cuda_bf16.h>
#include <math.h>
#include <stdint.h>

#define TOKENS 8192
#define DIM    4096
#define NEXP   256
#define TOPK   8

#define TM   64
#define BK   32                 // 2 x k16 per chunk
#define NCH  (DIM / BK)         // 128
#define NTH  512

#define ROWB   256              // 8 granules of 32B; granules 0..5 used (3 splits x 2 cq)
#define STAGE  (320 * ROWB)     // rows 0..63 = A, 64..319 = B  (81920 B)
#define SMEM_BYTES (2 * STAGE)  // 163840
#define LGS  264

// pre-split W: [c][n][6 granules x 32B] ; granule j = sp*2+cq, words perm (P0,P4,P1,P5,P2,P6,P3,P7)
__device__ __align__(16) char g_ws[NCH * NEXP * 192];

__device__ __forceinline__ uint32_t pack_bf16(__nv_bfloat16 lo, __nv_bfloat16 hi) {
    return ((uint32_t)__bfloat16_as_ushort(hi) << 16) | __bfloat16_as_ushort(lo);
}

__device__ __forceinline__ void mma_bf16(float* d,
                                         uint32_t a0, uint32_t a1, uint32_t a2, uint32_t a3,
                                         uint32_t b0, uint32_t b1) {
    asm volatile(
        "mma.sync.aligned.m16n8k16.row.col.f32.bf16.bf16.f32 "
        "{%0,%1,%2,%3},{%4,%5,%6,%7},{%8,%9},{%0,%1,%2,%3};"
        : "+f"(d[0]), "+f"(d[1]), "+f"(d[2]), "+f"(d[3])
        : "r"(a0), "r"(a1), "r"(a2), "r"(a3), "r"(b0), "r"(b1));
}

__device__ __forceinline__ uint32_t smem_u32(const void* p) {
    uint32_t a;
    asm("{ .reg .u64 t; cvta.to.shared.u64 t, %1; cvt.u32.u64 %0, t; }" : "=r"(a) : "l"(p));
    return a;
}
#define CP_ASYNC16(dst, src) \
    asm volatile("cp.async.cg.shared.global [%0], [%1], 16;" :: "r"(dst), "l"(src))
#define CP_COMMIT() asm volatile("cp.async.commit_group;" ::: "memory")
#define CP_WAIT0()  asm volatile("cp.async.wait_group 0;" ::: "memory")

__device__ __forceinline__ void split3(float v, uint16_t* h, uint16_t* m, uint16_t* l) {
    __nv_bfloat16 bh = __float2bfloat16_rn(v);
    float r1 = v - __bfloat162float(bh);
    __nv_bfloat16 bm = __float2bfloat16_rn(r1);
    __nv_bfloat16 bl = __float2bfloat16_rn(r1 - __bfloat162float(bm));
    *h = __bfloat16_as_ushort(bh);
    *m = __bfloat16_as_ushort(bm);
    *l = __bfloat16_as_ushort(bl);
}

// XLA logistic: 0.5 + 0.5 * tanh(0.5x)
__device__ __forceinline__ float xla_sigmoid(float v) {
    float x = 0.5f * v;
    float t;
    if (fabsf(x) < 0.0004f) {
        t = x;
    } else {
        float xc = fminf(fmaxf(x, -7.90531110763549805f), 7.90531110763549805f);
        float x2 = xc * xc;
        float p = -2.76076847742355e-16f;
        p = fmaf(p, x2, 2.00018790482477e-13f);
        p = fmaf(p, x2, -8.60467152213735e-11f);
        p = fmaf(p, x2, 5.12229709037114e-08f);
        p = fmaf(p, x2, 1.48572235717979e-05f);
        p = fmaf(p, x2, 6.37261928875436e-04f);
        p = fmaf(p, x2, 4.89352455891786e-03f);
        p = xc * p;
        float q = 1.19825839466702e-06f;
        q = fmaf(q, x2, 1.18534705686654e-04f);
        q = fmaf(q, x2, 2.26843463243900e-03f);
        q = fmaf(q, x2, 4.89352518554385e-03f);
        t = p / q;
    }
    return fmaf(0.5f, t, 0.5f);
}

// ============================================================================
// W pre-split: thread per (n, c); writes [c][n][192B]
// ============================================================================
__global__ __launch_bounds__(256) void wsplit_kernel(const float* __restrict__ w) {
    int j  = blockIdx.x * 256 + threadIdx.x;   // 32768
    int c  = j & 127;
    int n  = j >> 7;
    const float4* src = (const float4*)(w + (size_t)n * DIM + c * BK);
    float v[32];
    #pragma unroll
    for (int i = 0; i < 8; ++i) {
        float4 f = src[i];
        v[i*4+0] = f.x; v[i*4+1] = f.y; v[i*4+2] = f.z; v[i*4+3] = f.w;
    }
    uint16_t H[32], M[32], L[32];
    #pragma unroll
    for (int i = 0; i < 32; ++i) split3(v[i], &H[i], &M[i], &L[i]);

    // granule(sp,cq): 8 words = P[perm], perm = {0,4,1,5,2,6,3,7}, P_j = pack(v[cq*16+2j], v[..+2j+1])
    uint32_t* dst = (uint32_t*)(g_ws + ((size_t)c * NEXP + n) * 192);
    const int perm[8] = {0, 4, 1, 5, 2, 6, 3, 7};
    #pragma unroll
    for (int sp = 0; sp < 3; ++sp) {
        const uint16_t* S = (sp == 0) ? H : (sp == 1) ? M : L;
        #pragma unroll
        for (int cq = 0; cq < 2; ++cq) {
            #pragma unroll
            for (int wpos = 0; wpos < 8; ++wpos) {
                int pj = perm[wpos];
                int k0 = cq * 16 + 2 * pj;
                dst[(sp * 2 + cq) * 8 + wpos] =
                    ((uint32_t)S[k0 + 1] << 16) | S[k0];
            }
        }
    }
}

// ============================================================================
// main kernel
// ============================================================================
__global__ __launch_bounds__(NTH, 1)
void gate_bf16x3_kernel(const float* __restrict__ x,
                        float* __restrict__ out,
                        int write_idx)
{
    extern __shared__ char smem[];
    const uint32_t sb = smem_u32(smem);
    const int tid    = threadIdx.x;
    const int lane   = tid & 31;
    const int wid    = tid >> 5;
    const int warp_m = wid & 1;      // 2 x 32 tokens
    const int warp_n = wid >> 1;     // 8 x 32 experts
    const int t0     = blockIdx.x * TM;
    const int fr     = lane >> 2;
    const int fc     = lane & 3;

    float am[2][4][4], ac[2][4][4];
    #pragma unroll
    for (int tm = 0; tm < 2; ++tm)
        #pragma unroll
        for (int tn = 0; tn < 4; ++tn)
            #pragma unroll
            for (int q = 0; q < 4; ++q) { am[tm][tn][q] = 0.f; ac[tm][tn][q] = 0.f; }

    // fragment row bases
    int arow[2][2];
    #pragma unroll
    for (int tm = 0; tm < 2; ++tm) {
        arow[tm][0] = warp_m * 32 + tm * 16 + fr;
        arow[tm][1] = arow[tm][0] + 8;
    }
    int brow[4];
    #pragma unroll
    for (int tn = 0; tn < 4; ++tn) brow[tn] = 64 + warp_n * 32 + tn * 8 + fr;

    // x staging: thread -> row r = tid>>3, q = tid&7 (4 k-values at q*4)
    const int xr = tid >> 3;
    const int xq = tid & 7;
    const int xcq = xq >> 2;            // k16 half
    const int xj0 = (xq & 3) * 2;       // first pair index within the 16
    // word positions inside granule for pairs j0, j0+1:
    const int xp0 = (xj0 & 3) * 2 + (xj0 >> 2);
    const int xp1 = ((xj0 + 1) & 3) * 2 + ((xj0 + 1) >> 2);

    float4 ra;

    auto issue = [&](int c, int s) {
        // W: 3072 16B units
        const char* wsrc = g_ws + (size_t)c * (NEXP * 192);
        #pragma unroll
        for (int i = 0; i < 6; ++i) {
            int u  = tid + 512 * i;
            int n  = u / 12;
            int gi = u - n * 12;
            int gj = gi >> 1;                 // granule 0..5
            int hf = gi & 1;
            int r  = 64 + n;
            uint32_t dst = sb + (uint32_t)(s * STAGE + r * ROWB + ((gj ^ (r & 3)) * 32) + hf * 16);
            CP_ASYNC16(dst, (const void*)(wsrc + (size_t)u * 16));
        }
        CP_COMMIT();
        // x: load only (split+store deferred)
        ra = *(const float4*)(x + (size_t)(t0 + xr) * DIM + c * BK + xq * 4);
    };

    auto finish_x = [&](int s) {
        uint16_t H[4], M[4], L[4];
        split3(ra.x, &H[0], &M[0], &L[0]);
        split3(ra.y, &H[1], &M[1], &L[1]);
        split3(ra.z, &H[2], &M[2], &L[2]);
        split3(ra.w, &H[3], &M[3], &L[3]);
        uint32_t* base = (uint32_t*)(smem + s * STAGE + xr * ROWB);
        const int rx = xr & 3;
        #pragma unroll
        for (int sp = 0; sp < 3; ++sp) {
            const uint16_t* S = (sp == 0) ? H : (sp == 1) ? M : L;
            uint32_t* g = base + (((sp * 2 + xcq) ^ rx) * 8);
            g[xp0] = ((uint32_t)S[1] << 16) | S[0];
            g[xp1] = ((uint32_t)S[3] << 16) | S[2];
        }
    };

    // prologue
    issue(0, 0);
    finish_x(0);
    CP_WAIT0();
    __syncthreads();

    for (int c = 0; c < NCH; ++c) {
        const int s = c & 1;
        if (c + 1 < NCH) issue(c + 1, s ^ 1);

        const char* st = smem + s * STAGE;
        #pragma unroll
        for (int cq = 0; cq < 2; ++cq) {
            uint2 A[3][2][2];   // [sp][tm][hf]
            #pragma unroll
            for (int tm = 0; tm < 2; ++tm)
                #pragma unroll
                for (int hf = 0; hf < 2; ++hf) {
                    int r = arow[tm][hf];
                    const char* pr = st + r * ROWB;
                    const int rx = r & 3;
                    A[0][tm][hf] = *(const uint2*)(pr + (((0 * 2 + cq) ^ rx) * 32) + fc * 8);
                    A[1][tm][hf] = *(const uint2*)(pr + (((1 * 2 + cq) ^ rx) * 32) + fc * 8);
                    A[2][tm][hf] = *(const uint2*)(pr + (((2 * 2 + cq) ^ rx) * 32) + fc * 8);
                }
            #pragma unroll
            for (int tn = 0; tn < 4; ++tn) {
                int r = brow[tn];
                const char* pr = st + r * ROWB;
                const int rx = r & 3;
                uint2 bh = *(const uint2*)(pr + (((0 * 2 + cq) ^ rx) * 32) + fc * 8);
                uint2 bm = *(const uint2*)(pr + (((1 * 2 + cq) ^ rx) * 32) + fc * 8);
                uint2 bl = *(const uint2*)(pr + (((2 * 2 + cq) ^ rx) * 32) + fc * 8);
                #pragma unroll
                for (int tm = 0; tm < 2; ++tm) {
                    float* dm = am[tm][tn];
                    float* dc = ac[tm][tn];
                    uint2 ah0 = A[0][tm][0], ah1 = A[0][tm][1];
                    uint2 am0 = A[1][tm][0], am1 = A[1][tm][1];
                    uint2 al0 = A[2][tm][0], al1 = A[2][tm][1];
                    mma_bf16(dm, ah0.x, ah1.x, ah0.y, ah1.y, bh.x, bh.y);  // hh
                    mma_bf16(dc, ah0.x, ah1.x, ah0.y, ah1.y, bm.x, bm.y);  // hm
                    mma_bf16(dc, am0.x, am1.x, am0.y, am1.y, bh.x, bh.y);  // mh
                    mma_bf16(dc, am0.x, am1.x, am0.y, am1.y, bm.x, bm.y);  // mm
                    mma_bf16(dc, ah0.x, ah1.x, ah0.y, ah1.y, bl.x, bl.y);  // hl
                    mma_bf16(dc, al0.x, al1.x, al0.y, al1.y, bh.x, bh.y);  // lh
                }
            }
        }

        if (c + 1 < NCH) finish_x(s ^ 1);
        CP_WAIT0();
        __syncthreads();
    }

    // ---- epilogue: logits -> smem [64][LGS] ----
    float* lg = (float*)smem;
    #pragma unroll
    for (int tm = 0; tm < 2; ++tm) {
        int r = warp_m * 32 + tm * 16 + fr;
        #pragma unroll
        for (int tn = 0; tn < 4; ++tn) {
            int cc = warp_n * 32 + tn * 8 + fc * 2;
            float v0 = am[tm][tn][0] + ac[tm][tn][0];
            float v1 = am[tm][tn][1] + ac[tm][tn][1];
            float v2 = am[tm][tn][2] + ac[tm][tn][2];
            float v3 = am[tm][tn][3] + ac[tm][tn][3];
            *(float2*)(lg + (size_t)r * LGS + cc)       = make_float2(v0, v1);
            *(float2*)(lg + (size_t)(r + 8) * LGS + cc) = make_float2(v2, v3);
        }
    }
    __syncthreads();

    // ---- top-8 on sigmoid scores, lower-index tie-break ----
    #pragma unroll
    for (int it = 0; it < 4; ++it) {
        const int t = wid * 4 + it;
        float v[8];
        #pragma unroll
        for (int j = 0; j < 8; ++j)
            v[j] = xla_sigmoid(lg[(size_t)t * LGS + lane + j * 32]);

        float topv[8];
        int   topi[8];
        unsigned used = 0;

        #pragma unroll
        for (int r = 0; r < 8; ++r) {
            float best = -INFINITY;
            int   bidx = 0x7fffffff;
            #pragma unroll
            for (int j = 0; j < 8; ++j) {
                if (!((used >> j) & 1u)) {
                    float val = v[j];
                    int   id  = lane + j * 32;
                    if (val > best || (val == best && id < bidx)) { best = val; bidx = id; }
                }
            }
            #pragma unroll
            for (int off = 16; off > 0; off >>= 1) {
                float ov = __shfl_xor_sync(0xffffffffu, best, off);
                int   oi = __shfl_xor_sync(0xffffffffu, bidx, off);
                if (ov > best || (ov == best && oi < bidx)) { best = ov; bidx = oi; }
            }
            topv[r] = best;
            topi[r] = bidx;
            if ((bidx & 31) == lane) used |= 1u << (bidx >> 5);
        }

        float sum = 0.f;
        #pragma unroll
        for (int r = 0; r < 8; ++r) sum += topv[r];
        float inv = 1.f / sum;

        if (lane == 0) {
            int gt = t0 + t;
            #pragma unroll
            for (int r = 0; r < 8; ++r)
                out[(size_t)gt * TOPK + r] = topv[r] * inv;
            if (write_idx) {
                #pragma unroll
                for (int r = 0; r < 8; ++r)
                    out[(size_t)TOKENS * TOPK + (size_t)gt * TOPK + r] = (float)topi[r];
            }
        }
    }
}

extern "C" void kernel_launch(void* const* d_in, const int* in_sizes, int n_in,
                              void* d_out, int out_size)
{
    const float* x = (const float*)d_in[0];   // [TOKENS, DIM]
    const float* w = (const float*)d_in[1];   // [NEXP, DIM]
    float* out = (float*)d_out;

    int write_idx = (out_size >= 2 * TOKENS * TOPK) ? 1 : 0;

    cudaFuncSetAttribute(gate_bf16x3_kernel, cudaFuncAttributeMaxDynamicSharedMemorySize, SMEM_BYTES);

    wsplit_kernel<<<(NEXP * NCH) / 256, 256>>>(w);
    gate_bf16x3_kernel<<<TOKENS / TM, NTH, SMEM_BYTES>>>(x, out, write_idx);
}